// round 8
// baseline (speedup 1.0000x reference)
#include <cuda_runtime.h>
#include <cuda_bf16.h>
#include <math.h>
#include <stdint.h>

// ---------------------------------------------------------------------------
// Problem constants
// ---------------------------------------------------------------------------
#define B_   8
#define HW_  224
#define C_   192
#define WS_  7
#define SHIFT_ 3
#define NH_  6
#define HD_  32
#define NWIN_ 1024
#define NTOK_ 49
#define M_TOK 401408
#define DFF_ 768

// ---------------------------------------------------------------------------
// Scratch
// ---------------------------------------------------------------------------
__device__ __nv_bfloat16 g_win [401408 * 192];
__device__ __nv_bfloat16 g_big [401408 * 768];
__device__ float         g_xnew[401408 * 192];
// bf16 weights (converted once per launch)
__device__ __nv_bfloat16 g_wqkv[192 * 576];
__device__ __nv_bfloat16 g_wproj[192 * 192];
__device__ __nv_bfloat16 g_w1 [192 * 768];
__device__ __nv_bfloat16 g_w2 [768 * 192];

__device__ __forceinline__ uint32_t smem_u32(const void* p) {
    return (uint32_t)__cvta_generic_to_shared(p);
}
__device__ __forceinline__ void cp16(void* sdst, const void* gsrc) {
    asm volatile("cp.async.cg.shared.global [%0], [%1], 16;\n"
                 :: "r"(smem_u32(sdst)), "l"(gsrc));
}
__device__ __forceinline__ void cp_commit() {
    asm volatile("cp.async.commit_group;\n");
}
template <int N>
__device__ __forceinline__ void cp_wait() {
    asm volatile("cp.async.wait_group %0;\n" :: "n"(N));
}

// ---------------------------------------------------------------------------
// fp32 -> bf16 weight convert
// ---------------------------------------------------------------------------
__global__ void f2bf_k(const float* __restrict__ s, __nv_bfloat16* __restrict__ d, int n) {
    int i = blockIdx.x * 256 + threadIdx.x;
    if (i < n) d[i] = __float2bfloat16(s[i]);
}

// ---------------------------------------------------------------------------
// LN: one warp per token, bf16 output
// ---------------------------------------------------------------------------
__device__ __forceinline__ void warp_ln_row(const float* __restrict__ src,
                                            const float* __restrict__ w,
                                            const float* __restrict__ b,
                                            __nv_bfloat16* __restrict__ dst,
                                            int lane) {
    float v[6];
    float s = 0.f, ss = 0.f;
#pragma unroll
    for (int t = 0; t < 6; t++) {
        v[t] = src[lane + 32 * t];
        s += v[t];
        ss += v[t] * v[t];
    }
#pragma unroll
    for (int o = 16; o > 0; o >>= 1) {
        s  += __shfl_xor_sync(0xffffffffu, s,  o);
        ss += __shfl_xor_sync(0xffffffffu, ss, o);
    }
    float mu  = s * (1.f / 192.f);
    float var = ss * (1.f / 192.f) - mu * mu;
    float inv = rsqrtf(var + 1e-5f);
#pragma unroll
    for (int t = 0; t < 6; t++) {
        int c = lane + 32 * t;
        dst[c] = __float2bfloat16((v[t] - mu) * inv * w[c] + b[c]);
    }
}

__device__ __forceinline__ long long token_to_pixel_row(int token) {
    int bb  = token / (NWIN_ * NTOK_);
    int rem = token - bb * (NWIN_ * NTOK_);
    int wi  = rem / NTOK_;
    int n   = rem - wi * NTOK_;
    int wh = wi >> 5, ww = wi & 31;
    int r = n / 7, c = n - r * 7;
    int hh = wh * 7 + r + SHIFT_; if (hh >= HW_) hh -= HW_;
    int wp = ww * 7 + c + SHIFT_; if (wp >= HW_) wp -= HW_;
    return (long long)bb * (HW_ * HW_) + hh * HW_ + wp;
}

__global__ __launch_bounds__(256)
void ln1_window_k(const float* __restrict__ x,
                  const float* __restrict__ w, const float* __restrict__ b,
                  __nv_bfloat16* __restrict__ out) {
    int token = blockIdx.x * 8 + (threadIdx.x >> 5);
    int lane  = threadIdx.x & 31;
    long long src_row = token_to_pixel_row(token);
    warp_ln_row(x + src_row * C_, w, b, out + (long long)token * C_, lane);
}

__global__ __launch_bounds__(256)
void ln2_k(const float* __restrict__ x,
           const float* __restrict__ w, const float* __restrict__ b,
           __nv_bfloat16* __restrict__ out) {
    int token = blockIdx.x * 8 + (threadIdx.x >> 5);
    int lane  = threadIdx.x & 31;
    warp_ln_row(x + (long long)token * C_, w, b, out + (long long)token * C_, lane);
}

// ---------------------------------------------------------------------------
// BF16 tensor-core GEMM with 3-stage cp.async pipeline
// C = A(bf16)[M,K] @ B(bf16)[K,N] + bias
//   EPI 0: bias -> bf16          EPI 1: bias+GELU -> bf16
//   EPI 2: bias+scatter+residual -> fp32   EPI 3: bias+residual -> fp32
// BM=128 BN=64 BK=32; 8 warps (4m x 2n); warp tile 32x32; m16n8k16.
// ---------------------------------------------------------------------------
#define APAD 8
#define BPAD 8
#define STAGES 3

template <int EPI>
__global__ __launch_bounds__(256, 2)
void bgemm_k(const __nv_bfloat16* __restrict__ A, const __nv_bfloat16* __restrict__ Bw,
             const float* __restrict__ bias, void* __restrict__ Cout,
             int M, int N, int K, const float* __restrict__ res) {
    const int BM = 128, BN = 64, BK = 32;
    __shared__ __nv_bfloat16 As[STAGES][BM][BK + APAD];
    __shared__ __nv_bfloat16 Bs[STAGES][BK][BN + BPAD];

    int tid  = threadIdx.x;
    int warp = tid >> 5, lane = tid & 31;
    int wm = warp & 3, wn = warp >> 2;

    int brow = blockIdx.y, bcol = blockIdx.x;
    const __nv_bfloat16* Ab = A  + (size_t)brow * BM * K;
    const __nv_bfloat16* Bb = Bw + bcol * BN;

    // load indices
    int am = tid >> 2, acq = (tid & 3) * 8;          // A: 2 chunks (tid, tid+256)
    int am2 = (tid + 256) >> 2, acq2 = ((tid + 256) & 3) * 8;
    int bk = tid >> 3, bnq = (tid & 7) * 8;          // B: 1 chunk

    float acc[2][4][4];
#pragma unroll
    for (int i = 0; i < 2; i++)
#pragma unroll
        for (int j = 0; j < 4; j++)
#pragma unroll
            for (int l = 0; l < 4; l++) acc[i][j][l] = 0.f;

    const int ntiles = K / BK;

    // prologue: issue STAGES-1 tile loads
#pragma unroll
    for (int s = 0; s < STAGES - 1; s++) {
        int k0 = s * BK;
        cp16(&As[s][am ][acq ], Ab + (size_t)am  * K + k0 + acq );
        cp16(&As[s][am2][acq2], Ab + (size_t)am2 * K + k0 + acq2);
        cp16(&Bs[s][bk][bnq], Bb + (size_t)(k0 + bk) * N + bnq);
        cp_commit();
    }

    int a_row_lane = ((lane >> 3) & 1) * 8 + (lane & 7);
    int a_kof_lane = (lane >> 4) * 8;

    int stage = 0;
    for (int t = 0; t < ntiles; t++) {
        cp_wait<STAGES - 2>();
        __syncthreads();

        // issue load for tile t+STAGES-1
        int tn = t + STAGES - 1;
        if (tn < ntiles) {
            int sn = stage + STAGES - 1; if (sn >= STAGES) sn -= STAGES;
            int k0 = tn * BK;
            cp16(&As[sn][am ][acq ], Ab + (size_t)am  * K + k0 + acq );
            cp16(&As[sn][am2][acq2], Ab + (size_t)am2 * K + k0 + acq2);
            cp16(&Bs[sn][bk][bnq], Bb + (size_t)(k0 + bk) * N + bnq);
        }
        cp_commit();

        // compute tile t from smem stage
#pragma unroll
        for (int ks = 0; ks < 2; ks++) {
            int kk = ks * 16;
            uint32_t af[2][4], bfr[2][4];
#pragma unroll
            for (int mi = 0; mi < 2; mi++) {
                int mrow = wm * 32 + mi * 16 + a_row_lane;
                uint32_t addr = smem_u32(&As[stage][mrow][kk + a_kof_lane]);
                asm volatile("ldmatrix.sync.aligned.m8n8.x4.shared.b16 "
                             "{%0,%1,%2,%3}, [%4];"
                             : "=r"(af[mi][0]), "=r"(af[mi][1]),
                               "=r"(af[mi][2]), "=r"(af[mi][3])
                             : "r"(addr));
            }
#pragma unroll
            for (int ng = 0; ng < 2; ng++) {
                int ncol = wn * 32 + ng * 16 + a_kof_lane;
                uint32_t addr = smem_u32(&Bs[stage][kk + a_row_lane][ncol]);
                asm volatile("ldmatrix.sync.aligned.m8n8.x4.trans.shared.b16 "
                             "{%0,%1,%2,%3}, [%4];"
                             : "=r"(bfr[ng][0]), "=r"(bfr[ng][1]),
                               "=r"(bfr[ng][2]), "=r"(bfr[ng][3])
                             : "r"(addr));
            }
#pragma unroll
            for (int mi = 0; mi < 2; mi++)
#pragma unroll
                for (int ni = 0; ni < 4; ni++) {
                    uint32_t b0 = bfr[ni >> 1][(ni & 1) * 2 + 0];
                    uint32_t b1 = bfr[ni >> 1][(ni & 1) * 2 + 1];
                    asm volatile(
                        "mma.sync.aligned.m16n8k16.row.col.f32.bf16.bf16.f32 "
                        "{%0,%1,%2,%3}, {%4,%5,%6,%7}, {%8,%9}, {%0,%1,%2,%3};"
                        : "+f"(acc[mi][ni][0]), "+f"(acc[mi][ni][1]),
                          "+f"(acc[mi][ni][2]), "+f"(acc[mi][ni][3])
                        : "r"(af[mi][0]), "r"(af[mi][1]),
                          "r"(af[mi][2]), "r"(af[mi][3]),
                          "r"(b0), "r"(b1));
                }
        }
        __syncthreads();
        stage = stage + 1; if (stage >= STAGES) stage -= STAGES;
    }

    // ------------------------------ epilogue ------------------------------
    int g  = lane >> 2;
    int tg = lane & 3;
#pragma unroll
    for (int mi = 0; mi < 2; mi++) {
        int row0 = brow * BM + wm * 32 + mi * 16 + g;
        int row1 = row0 + 8;
        long long d0 = 0, d1 = 0;
        if (EPI == 2) { d0 = token_to_pixel_row(row0); d1 = token_to_pixel_row(row1); }
#pragma unroll
        for (int ni = 0; ni < 4; ni++) {
            int col = bcol * BN + wn * 32 + ni * 8 + tg * 2;
            float bx = bias[col], by = bias[col + 1];
            float v0 = acc[mi][ni][0] + bx, v1 = acc[mi][ni][1] + by;
            float v2 = acc[mi][ni][2] + bx, v3 = acc[mi][ni][3] + by;
            if (EPI == 1) {
                v0 = 0.5f * v0 * (1.f + erff(v0 * 0.70710678118654752f));
                v1 = 0.5f * v1 * (1.f + erff(v1 * 0.70710678118654752f));
                v2 = 0.5f * v2 * (1.f + erff(v2 * 0.70710678118654752f));
                v3 = 0.5f * v3 * (1.f + erff(v3 * 0.70710678118654752f));
            }
            if (EPI == 0 || EPI == 1) {
                __nv_bfloat16* C = (__nv_bfloat16*)Cout;
                *(__nv_bfloat162*)(C + (size_t)row0 * N + col) = __floats2bfloat162_rn(v0, v1);
                *(__nv_bfloat162*)(C + (size_t)row1 * N + col) = __floats2bfloat162_rn(v2, v3);
            } else if (EPI == 2) {
                float* C = (float*)Cout;
                float2 r0 = *(const float2*)(res + d0 * C_ + col);
                float2 r1 = *(const float2*)(res + d1 * C_ + col);
                *(float2*)(C + d0 * C_ + col) = make_float2(v0 + r0.x, v1 + r0.y);
                *(float2*)(C + d1 * C_ + col) = make_float2(v2 + r1.x, v3 + r1.y);
            } else {
                float* C = (float*)Cout;
                float2 r0 = *(const float2*)(res + (size_t)row0 * N + col);
                float2 r1 = *(const float2*)(res + (size_t)row1 * N + col);
                *(float2*)(C + (size_t)row0 * N + col) = make_float2(v0 + r0.x, v1 + r0.y);
                *(float2*)(C + (size_t)row1 * N + col) = make_float2(v2 + r1.x, v3 + r1.y);
            }
        }
    }
}

// ---------------------------------------------------------------------------
// Windowed attention (bf16 in/out, fp32 math)
// ---------------------------------------------------------------------------
__global__ __launch_bounds__(128)
void attn_k(const __nv_bfloat16* __restrict__ qkv, const float* __restrict__ rpb,
            __nv_bfloat16* __restrict__ out) {
    int wg = blockIdx.x;
    int h  = blockIdx.y;
    int wi = wg & (NWIN_ - 1);
    int wh = wi >> 5, ww = wi & 31;

    __shared__ float sq[49][33], sk[49][33], sv[49][33];
    __shared__ float sp[4][49];
    __shared__ int   sreg[49];

    int tid = threadIdx.x;
    long long base = (long long)wg * NTOK_ * 576 + h * HD_;

    for (int idx = tid; idx < 49 * 32; idx += 128) {
        int n = idx >> 5, d = idx & 31;
        long long rb = base + (long long)n * 576 + d;
        sq[n][d] = __bfloat162float(qkv[rb]);
        sk[n][d] = __bfloat162float(qkv[rb + 192]);
        sv[n][d] = __bfloat162float(qkv[rb + 384]);
    }
    if (tid < 49) {
        int r = tid / 7, c = tid - (tid / 7) * 7;
        int gh = wh * 7 + r, gw = ww * 7 + c;
        int hid = gh < (HW_ - WS_) ? 0 : (gh < (HW_ - SHIFT_) ? 1 : 2);
        int wid = gw < (HW_ - WS_) ? 0 : (gw < (HW_ - SHIFT_) ? 1 : 2);
        sreg[tid] = hid * 3 + wid;
    }
    __syncthreads();

    int warp = tid >> 5, lane = tid & 31;
    const float scale = 0.1767766952966369f;

    for (int i = warp; i < 49; i += 4) {
        int r1 = i / 7, c1 = i - (i / 7) * 7;
        int regi = sreg[i];

        float s1, s2 = -1e30f;
        {
            int j = lane;
            float dp = 0.f;
#pragma unroll
            for (int d = 0; d < 32; d++) dp += sq[i][d] * sk[j][d];
            int r2 = j / 7, c2 = j - (j / 7) * 7;
            int rel = (r1 - r2 + 6) * 13 + (c1 - c2 + 6);
            float bv = rpb[rel * NH_ + h];
            float mk = (sreg[j] != regi) ? -100.f : 0.f;
            s1 = dp * scale + bv + mk;
        }
        if (lane < 17) {
            int j = lane + 32;
            float dp = 0.f;
#pragma unroll
            for (int d = 0; d < 32; d++) dp += sq[i][d] * sk[j][d];
            int r2 = j / 7, c2 = j - (j / 7) * 7;
            int rel = (r1 - r2 + 6) * 13 + (c1 - c2 + 6);
            float bv = rpb[rel * NH_ + h];
            float mk = (sreg[j] != regi) ? -100.f : 0.f;
            s2 = dp * scale + bv + mk;
        }
        float mx = fmaxf(s1, s2);
#pragma unroll
        for (int o = 16; o > 0; o >>= 1)
            mx = fmaxf(mx, __shfl_xor_sync(0xffffffffu, mx, o));
        float e1 = __expf(s1 - mx);
        float e2 = (lane < 17) ? __expf(s2 - mx) : 0.f;
        float sum = e1 + e2;
#pragma unroll
        for (int o = 16; o > 0; o >>= 1)
            sum += __shfl_xor_sync(0xffffffffu, sum, o);
        float inv = 1.f / sum;
        sp[warp][lane] = e1 * inv;
        if (lane < 17) sp[warp][lane + 32] = e2 * inv;
        __syncwarp();

        float acc = 0.f;
#pragma unroll 7
        for (int j = 0; j < 49; j++) acc += sp[warp][j] * sv[j][lane];

        long long orow = ((long long)wg * NTOK_ + i) * C_ + h * HD_ + lane;
        out[orow] = __float2bfloat16(acc);
        __syncwarp();
    }
}

// ---------------------------------------------------------------------------
// Launch
// ---------------------------------------------------------------------------
extern "C" void kernel_launch(void* const* d_in, const int* in_sizes, int n_in,
                              void* d_out, int out_size) {
    const float* x      = (const float*)d_in[0];
    const float* qkv_w  = (const float*)d_in[3];
    const float* qkv_b  = (const float*)d_in[4];
    const float* proj_w = (const float*)d_in[5];
    const float* proj_b = (const float*)d_in[6];
    const float* rpb    = (const float*)d_in[7];
    const float* n1w    = (const float*)d_in[8];
    const float* n1b    = (const float*)d_in[9];
    const float* n2w    = (const float*)d_in[10];
    const float* n2b    = (const float*)d_in[11];
    const float* w1     = (const float*)d_in[12];
    const float* b1     = (const float*)d_in[13];
    const float* w2     = (const float*)d_in[14];
    const float* b2     = (const float*)d_in[15];
    float* out = (float*)d_out;

    __nv_bfloat16 *win = nullptr, *big = nullptr;
    __nv_bfloat16 *wqkv = nullptr, *wproj = nullptr, *bw1 = nullptr, *bw2 = nullptr;
    float *xnew = nullptr;
    cudaGetSymbolAddress((void**)&win,   g_win);
    cudaGetSymbolAddress((void**)&big,   g_big);
    cudaGetSymbolAddress((void**)&xnew,  g_xnew);
    cudaGetSymbolAddress((void**)&wqkv,  g_wqkv);
    cudaGetSymbolAddress((void**)&wproj, g_wproj);
    cudaGetSymbolAddress((void**)&bw1,   g_w1);
    cudaGetSymbolAddress((void**)&bw2,   g_w2);

    const int M = M_TOK;
    const int MB = M / 128;

    // weight conversion (cheap)
    f2bf_k<<<(192 * 576 + 255) / 256, 256>>>(qkv_w,  wqkv,  192 * 576);
    f2bf_k<<<(192 * 192 + 255) / 256, 256>>>(proj_w, wproj, 192 * 192);
    f2bf_k<<<(192 * 768 + 255) / 256, 256>>>(w1,     bw1,   192 * 768);
    f2bf_k<<<(768 * 192 + 255) / 256, 256>>>(w2,     bw2,   768 * 192);

    ln1_window_k<<<M / 8, 256>>>(x, n1w, n1b, win);
    bgemm_k<0><<<dim3(576 / 64, MB), 256>>>(win, wqkv, qkv_b, big, M, 576, 192, nullptr);
    attn_k<<<dim3(B_ * NWIN_, NH_), 128>>>(big, rpb, win);
    bgemm_k<2><<<dim3(192 / 64, MB), 256>>>(win, wproj, proj_b, xnew, M, 192, 192, x);
    ln2_k<<<M / 8, 256>>>(xnew, n2w, n2b, win);
    bgemm_k<1><<<dim3(768 / 64, MB), 256>>>(win, bw1, b1, big, M, 768, 192, nullptr);
    bgemm_k<3><<<dim3(192 / 64, MB), 256>>>(big, bw2, b2, out, M, 192, 768, xnew);
}

// round 9
// speedup vs baseline: 1.0018x; 1.0018x over previous
#include <cuda_runtime.h>
#include <cuda_bf16.h>
#include <math.h>
#include <stdint.h>

// ---------------------------------------------------------------------------
// Problem constants
// ---------------------------------------------------------------------------
#define B_   8
#define HW_  224
#define C_   192
#define WS_  7
#define SHIFT_ 3
#define NH_  6
#define HD_  32
#define NWIN_ 1024
#define NTOK_ 49
#define M_TOK 401408
#define DFF_ 768

// ---------------------------------------------------------------------------
// Scratch
// ---------------------------------------------------------------------------
__device__ __nv_bfloat16 g_win [401408 * 192];
__device__ __nv_bfloat16 g_big [401408 * 768];
__device__ float         g_xnew[401408 * 192];
// bf16 weights (converted once per launch)
__device__ __nv_bfloat16 g_wqkv[192 * 576];
__device__ __nv_bfloat16 g_wproj[192 * 192];
__device__ __nv_bfloat16 g_w1 [192 * 768];
__device__ __nv_bfloat16 g_w2 [768 * 192];

__device__ __forceinline__ uint32_t smem_u32(const void* p) {
    return (uint32_t)__cvta_generic_to_shared(p);
}
__device__ __forceinline__ void cp16(void* sdst, const void* gsrc) {
    asm volatile("cp.async.cg.shared.global [%0], [%1], 16;\n"
                 :: "r"(smem_u32(sdst)), "l"(gsrc));
}
__device__ __forceinline__ void cp_commit() {
    asm volatile("cp.async.commit_group;\n");
}
template <int N>
__device__ __forceinline__ void cp_wait() {
    asm volatile("cp.async.wait_group %0;\n" :: "n"(N));
}

// ---------------------------------------------------------------------------
// fp32 -> bf16 weight convert
// ---------------------------------------------------------------------------
__global__ void f2bf_k(const float* __restrict__ s, __nv_bfloat16* __restrict__ d, int n) {
    int i = blockIdx.x * 256 + threadIdx.x;
    if (i < n) d[i] = __float2bfloat16(s[i]);
}

// ---------------------------------------------------------------------------
// LN: one warp per token, bf16 output
// ---------------------------------------------------------------------------
__device__ __forceinline__ void warp_ln_row(const float* __restrict__ src,
                                            const float* __restrict__ w,
                                            const float* __restrict__ b,
                                            __nv_bfloat16* __restrict__ dst,
                                            int lane) {
    float v[6];
    float s = 0.f, ss = 0.f;
#pragma unroll
    for (int t = 0; t < 6; t++) {
        v[t] = src[lane + 32 * t];
        s += v[t];
        ss += v[t] * v[t];
    }
#pragma unroll
    for (int o = 16; o > 0; o >>= 1) {
        s  += __shfl_xor_sync(0xffffffffu, s,  o);
        ss += __shfl_xor_sync(0xffffffffu, ss, o);
    }
    float mu  = s * (1.f / 192.f);
    float var = ss * (1.f / 192.f) - mu * mu;
    float inv = rsqrtf(var + 1e-5f);
#pragma unroll
    for (int t = 0; t < 6; t++) {
        int c = lane + 32 * t;
        dst[c] = __float2bfloat16((v[t] - mu) * inv * w[c] + b[c]);
    }
}

__device__ __forceinline__ long long token_to_pixel_row(int token) {
    int bb  = token / (NWIN_ * NTOK_);
    int rem = token - bb * (NWIN_ * NTOK_);
    int wi  = rem / NTOK_;
    int n   = rem - wi * NTOK_;
    int wh = wi >> 5, ww = wi & 31;
    int r = n / 7, c = n - r * 7;
    int hh = wh * 7 + r + SHIFT_; if (hh >= HW_) hh -= HW_;
    int wp = ww * 7 + c + SHIFT_; if (wp >= HW_) wp -= HW_;
    return (long long)bb * (HW_ * HW_) + hh * HW_ + wp;
}

__global__ __launch_bounds__(256)
void ln1_window_k(const float* __restrict__ x,
                  const float* __restrict__ w, const float* __restrict__ b,
                  __nv_bfloat16* __restrict__ out) {
    int token = blockIdx.x * 8 + (threadIdx.x >> 5);
    int lane  = threadIdx.x & 31;
    long long src_row = token_to_pixel_row(token);
    warp_ln_row(x + src_row * C_, w, b, out + (long long)token * C_, lane);
}

__global__ __launch_bounds__(256)
void ln2_k(const float* __restrict__ x,
           const float* __restrict__ w, const float* __restrict__ b,
           __nv_bfloat16* __restrict__ out) {
    int token = blockIdx.x * 8 + (threadIdx.x >> 5);
    int lane  = threadIdx.x & 31;
    warp_ln_row(x + (long long)token * C_, w, b, out + (long long)token * C_, lane);
}

// ---------------------------------------------------------------------------
// BF16 tensor-core GEMM with 3-stage cp.async pipeline
// C = A(bf16)[M,K] @ B(bf16)[K,N] + bias
//   EPI 0: bias -> bf16          EPI 1: bias+GELU -> bf16
//   EPI 2: bias+scatter+residual -> fp32   EPI 3: bias+residual -> fp32
// BM=128 BN=64 BK=32; 8 warps (4m x 2n); warp tile 32x32; m16n8k16.
// ---------------------------------------------------------------------------
#define APAD 8
#define BPAD 8
#define STAGES 3

template <int EPI>
__global__ __launch_bounds__(256, 2)
void bgemm_k(const __nv_bfloat16* __restrict__ A, const __nv_bfloat16* __restrict__ Bw,
             const float* __restrict__ bias, void* __restrict__ Cout,
             int M, int N, int K, const float* __restrict__ res) {
    const int BM = 128, BN = 64, BK = 32;
    __shared__ __nv_bfloat16 As[STAGES][BM][BK + APAD];
    __shared__ __nv_bfloat16 Bs[STAGES][BK][BN + BPAD];

    int tid  = threadIdx.x;
    int warp = tid >> 5, lane = tid & 31;
    int wm = warp & 3, wn = warp >> 2;

    int brow = blockIdx.y, bcol = blockIdx.x;
    const __nv_bfloat16* Ab = A  + (size_t)brow * BM * K;
    const __nv_bfloat16* Bb = Bw + bcol * BN;

    // load indices
    int am = tid >> 2, acq = (tid & 3) * 8;          // A: 2 chunks (tid, tid+256)
    int am2 = (tid + 256) >> 2, acq2 = ((tid + 256) & 3) * 8;
    int bk = tid >> 3, bnq = (tid & 7) * 8;          // B: 1 chunk

    float acc[2][4][4];
#pragma unroll
    for (int i = 0; i < 2; i++)
#pragma unroll
        for (int j = 0; j < 4; j++)
#pragma unroll
            for (int l = 0; l < 4; l++) acc[i][j][l] = 0.f;

    const int ntiles = K / BK;

    // prologue: issue STAGES-1 tile loads
#pragma unroll
    for (int s = 0; s < STAGES - 1; s++) {
        int k0 = s * BK;
        cp16(&As[s][am ][acq ], Ab + (size_t)am  * K + k0 + acq );
        cp16(&As[s][am2][acq2], Ab + (size_t)am2 * K + k0 + acq2);
        cp16(&Bs[s][bk][bnq], Bb + (size_t)(k0 + bk) * N + bnq);
        cp_commit();
    }

    int a_row_lane = ((lane >> 3) & 1) * 8 + (lane & 7);
    int a_kof_lane = (lane >> 4) * 8;

    int stage = 0;
    for (int t = 0; t < ntiles; t++) {
        cp_wait<STAGES - 2>();
        __syncthreads();

        // issue load for tile t+STAGES-1
        int tn = t + STAGES - 1;
        if (tn < ntiles) {
            int sn = stage + STAGES - 1; if (sn >= STAGES) sn -= STAGES;
            int k0 = tn * BK;
            cp16(&As[sn][am ][acq ], Ab + (size_t)am  * K + k0 + acq );
            cp16(&As[sn][am2][acq2], Ab + (size_t)am2 * K + k0 + acq2);
            cp16(&Bs[sn][bk][bnq], Bb + (size_t)(k0 + bk) * N + bnq);
        }
        cp_commit();

        // compute tile t from smem stage
#pragma unroll
        for (int ks = 0; ks < 2; ks++) {
            int kk = ks * 16;
            uint32_t af[2][4], bfr[2][4];
#pragma unroll
            for (int mi = 0; mi < 2; mi++) {
                int mrow = wm * 32 + mi * 16 + a_row_lane;
                uint32_t addr = smem_u32(&As[stage][mrow][kk + a_kof_lane]);
                asm volatile("ldmatrix.sync.aligned.m8n8.x4.shared.b16 "
                             "{%0,%1,%2,%3}, [%4];"
                             : "=r"(af[mi][0]), "=r"(af[mi][1]),
                               "=r"(af[mi][2]), "=r"(af[mi][3])
                             : "r"(addr));
            }
#pragma unroll
            for (int ng = 0; ng < 2; ng++) {
                int ncol = wn * 32 + ng * 16 + a_kof_lane;
                uint32_t addr = smem_u32(&Bs[stage][kk + a_row_lane][ncol]);
                asm volatile("ldmatrix.sync.aligned.m8n8.x4.trans.shared.b16 "
                             "{%0,%1,%2,%3}, [%4];"
                             : "=r"(bfr[ng][0]), "=r"(bfr[ng][1]),
                               "=r"(bfr[ng][2]), "=r"(bfr[ng][3])
                             : "r"(addr));
            }
#pragma unroll
            for (int mi = 0; mi < 2; mi++)
#pragma unroll
                for (int ni = 0; ni < 4; ni++) {
                    uint32_t b0 = bfr[ni >> 1][(ni & 1) * 2 + 0];
                    uint32_t b1 = bfr[ni >> 1][(ni & 1) * 2 + 1];
                    asm volatile(
                        "mma.sync.aligned.m16n8k16.row.col.f32.bf16.bf16.f32 "
                        "{%0,%1,%2,%3}, {%4,%5,%6,%7}, {%8,%9}, {%0,%1,%2,%3};"
                        : "+f"(acc[mi][ni][0]), "+f"(acc[mi][ni][1]),
                          "+f"(acc[mi][ni][2]), "+f"(acc[mi][ni][3])
                        : "r"(af[mi][0]), "r"(af[mi][1]),
                          "r"(af[mi][2]), "r"(af[mi][3]),
                          "r"(b0), "r"(b1));
                }
        }
        __syncthreads();
        stage = stage + 1; if (stage >= STAGES) stage -= STAGES;
    }

    // ------------------------------ epilogue ------------------------------
    int g  = lane >> 2;
    int tg = lane & 3;
#pragma unroll
    for (int mi = 0; mi < 2; mi++) {
        int row0 = brow * BM + wm * 32 + mi * 16 + g;
        int row1 = row0 + 8;
        long long d0 = 0, d1 = 0;
        if (EPI == 2) { d0 = token_to_pixel_row(row0); d1 = token_to_pixel_row(row1); }
#pragma unroll
        for (int ni = 0; ni < 4; ni++) {
            int col = bcol * BN + wn * 32 + ni * 8 + tg * 2;
            float bx = bias[col], by = bias[col + 1];
            float v0 = acc[mi][ni][0] + bx, v1 = acc[mi][ni][1] + by;
            float v2 = acc[mi][ni][2] + bx, v3 = acc[mi][ni][3] + by;
            if (EPI == 1) {
                v0 = 0.5f * v0 * (1.f + erff(v0 * 0.70710678118654752f));
                v1 = 0.5f * v1 * (1.f + erff(v1 * 0.70710678118654752f));
                v2 = 0.5f * v2 * (1.f + erff(v2 * 0.70710678118654752f));
                v3 = 0.5f * v3 * (1.f + erff(v3 * 0.70710678118654752f));
            }
            if (EPI == 0 || EPI == 1) {
                __nv_bfloat16* C = (__nv_bfloat16*)Cout;
                *(__nv_bfloat162*)(C + (size_t)row0 * N + col) = __floats2bfloat162_rn(v0, v1);
                *(__nv_bfloat162*)(C + (size_t)row1 * N + col) = __floats2bfloat162_rn(v2, v3);
            } else if (EPI == 2) {
                float* C = (float*)Cout;
                float2 r0 = *(const float2*)(res + d0 * C_ + col);
                float2 r1 = *(const float2*)(res + d1 * C_ + col);
                *(float2*)(C + d0 * C_ + col) = make_float2(v0 + r0.x, v1 + r0.y);
                *(float2*)(C + d1 * C_ + col) = make_float2(v2 + r1.x, v3 + r1.y);
            } else {
                float* C = (float*)Cout;
                float2 r0 = *(const float2*)(res + (size_t)row0 * N + col);
                float2 r1 = *(const float2*)(res + (size_t)row1 * N + col);
                *(float2*)(C + (size_t)row0 * N + col) = make_float2(v0 + r0.x, v1 + r0.y);
                *(float2*)(C + (size_t)row1 * N + col) = make_float2(v2 + r1.x, v3 + r1.y);
            }
        }
    }
}

// ---------------------------------------------------------------------------
// Windowed attention (bf16 in/out, fp32 math)
// ---------------------------------------------------------------------------
__global__ __launch_bounds__(128)
void attn_k(const __nv_bfloat16* __restrict__ qkv, const float* __restrict__ rpb,
            __nv_bfloat16* __restrict__ out) {
    int wg = blockIdx.x;
    int h  = blockIdx.y;
    int wi = wg & (NWIN_ - 1);
    int wh = wi >> 5, ww = wi & 31;

    __shared__ float sq[49][33], sk[49][33], sv[49][33];
    __shared__ float sp[4][49];
    __shared__ int   sreg[49];

    int tid = threadIdx.x;
    long long base = (long long)wg * NTOK_ * 576 + h * HD_;

    for (int idx = tid; idx < 49 * 32; idx += 128) {
        int n = idx >> 5, d = idx & 31;
        long long rb = base + (long long)n * 576 + d;
        sq[n][d] = __bfloat162float(qkv[rb]);
        sk[n][d] = __bfloat162float(qkv[rb + 192]);
        sv[n][d] = __bfloat162float(qkv[rb + 384]);
    }
    if (tid < 49) {
        int r = tid / 7, c = tid - (tid / 7) * 7;
        int gh = wh * 7 + r, gw = ww * 7 + c;
        int hid = gh < (HW_ - WS_) ? 0 : (gh < (HW_ - SHIFT_) ? 1 : 2);
        int wid = gw < (HW_ - WS_) ? 0 : (gw < (HW_ - SHIFT_) ? 1 : 2);
        sreg[tid] = hid * 3 + wid;
    }
    __syncthreads();

    int warp = tid >> 5, lane = tid & 31;
    const float scale = 0.1767766952966369f;

    for (int i = warp; i < 49; i += 4) {
        int r1 = i / 7, c1 = i - (i / 7) * 7;
        int regi = sreg[i];

        float s1, s2 = -1e30f;
        {
            int j = lane;
            float dp = 0.f;
#pragma unroll
            for (int d = 0; d < 32; d++) dp += sq[i][d] * sk[j][d];
            int r2 = j / 7, c2 = j - (j / 7) * 7;
            int rel = (r1 - r2 + 6) * 13 + (c1 - c2 + 6);
            float bv = rpb[rel * NH_ + h];
            float mk = (sreg[j] != regi) ? -100.f : 0.f;
            s1 = dp * scale + bv + mk;
        }
        if (lane < 17) {
            int j = lane + 32;
            float dp = 0.f;
#pragma unroll
            for (int d = 0; d < 32; d++) dp += sq[i][d] * sk[j][d];
            int r2 = j / 7, c2 = j - (j / 7) * 7;
            int rel = (r1 - r2 + 6) * 13 + (c1 - c2 + 6);
            float bv = rpb[rel * NH_ + h];
            float mk = (sreg[j] != regi) ? -100.f : 0.f;
            s2 = dp * scale + bv + mk;
        }
        float mx = fmaxf(s1, s2);
#pragma unroll
        for (int o = 16; o > 0; o >>= 1)
            mx = fmaxf(mx, __shfl_xor_sync(0xffffffffu, mx, o));
        float e1 = __expf(s1 - mx);
        float e2 = (lane < 17) ? __expf(s2 - mx) : 0.f;
        float sum = e1 + e2;
#pragma unroll
        for (int o = 16; o > 0; o >>= 1)
            sum += __shfl_xor_sync(0xffffffffu, sum, o);
        float inv = 1.f / sum;
        sp[warp][lane] = e1 * inv;
        if (lane < 17) sp[warp][lane + 32] = e2 * inv;
        __syncwarp();

        float acc = 0.f;
#pragma unroll 7
        for (int j = 0; j < 49; j++) acc += sp[warp][j] * sv[j][lane];

        long long orow = ((long long)wg * NTOK_ + i) * C_ + h * HD_ + lane;
        out[orow] = __float2bfloat16(acc);
        __syncwarp();
    }
}

// ---------------------------------------------------------------------------
// Launch
// ---------------------------------------------------------------------------
extern "C" void kernel_launch(void* const* d_in, const int* in_sizes, int n_in,
                              void* d_out, int out_size) {
    const float* x      = (const float*)d_in[0];
    const float* qkv_w  = (const float*)d_in[3];
    const float* qkv_b  = (const float*)d_in[4];
    const float* proj_w = (const float*)d_in[5];
    const float* proj_b = (const float*)d_in[6];
    const float* rpb    = (const float*)d_in[7];
    const float* n1w    = (const float*)d_in[8];
    const float* n1b    = (const float*)d_in[9];
    const float* n2w    = (const float*)d_in[10];
    const float* n2b    = (const float*)d_in[11];
    const float* w1     = (const float*)d_in[12];
    const float* b1     = (const float*)d_in[13];
    const float* w2     = (const float*)d_in[14];
    const float* b2     = (const float*)d_in[15];
    float* out = (float*)d_out;

    __nv_bfloat16 *win = nullptr, *big = nullptr;
    __nv_bfloat16 *wqkv = nullptr, *wproj = nullptr, *bw1 = nullptr, *bw2 = nullptr;
    float *xnew = nullptr;
    cudaGetSymbolAddress((void**)&win,   g_win);
    cudaGetSymbolAddress((void**)&big,   g_big);
    cudaGetSymbolAddress((void**)&xnew,  g_xnew);
    cudaGetSymbolAddress((void**)&wqkv,  g_wqkv);
    cudaGetSymbolAddress((void**)&wproj, g_wproj);
    cudaGetSymbolAddress((void**)&bw1,   g_w1);
    cudaGetSymbolAddress((void**)&bw2,   g_w2);

    const int M = M_TOK;
    const int MB = M / 128;

    // weight conversion (cheap)
    f2bf_k<<<(192 * 576 + 255) / 256, 256>>>(qkv_w,  wqkv,  192 * 576);
    f2bf_k<<<(192 * 192 + 255) / 256, 256>>>(proj_w, wproj, 192 * 192);
    f2bf_k<<<(192 * 768 + 255) / 256, 256>>>(w1,     bw1,   192 * 768);
    f2bf_k<<<(768 * 192 + 255) / 256, 256>>>(w2,     bw2,   768 * 192);

    ln1_window_k<<<M / 8, 256>>>(x, n1w, n1b, win);
    bgemm_k<0><<<dim3(576 / 64, MB), 256>>>(win, wqkv, qkv_b, big, M, 576, 192, nullptr);
    attn_k<<<dim3(B_ * NWIN_, NH_), 128>>>(big, rpb, win);
    bgemm_k<2><<<dim3(192 / 64, MB), 256>>>(win, wproj, proj_b, xnew, M, 192, 192, x);
    ln2_k<<<M / 8, 256>>>(xnew, n2w, n2b, win);
    bgemm_k<1><<<dim3(768 / 64, MB), 256>>>(win, bw1, b1, big, M, 768, 192, nullptr);
    bgemm_k<3><<<dim3(192 / 64, MB), 256>>>(big, bw2, b2, out, M, 192, 768, xnew);
}

// round 10
// speedup vs baseline: 1.0019x; 1.0001x over previous
#include <cuda_runtime.h>
#include <cuda_bf16.h>
#include <math.h>
#include <stdint.h>

// ---------------------------------------------------------------------------
// Problem constants
// ---------------------------------------------------------------------------
#define B_   8
#define HW_  224
#define C_   192
#define WS_  7
#define SHIFT_ 3
#define NH_  6
#define HD_  32
#define NWIN_ 1024
#define NTOK_ 49
#define M_TOK 401408
#define DFF_ 768

// ---------------------------------------------------------------------------
// Scratch
// ---------------------------------------------------------------------------
__device__ __nv_bfloat16 g_win [401408 * 192];
__device__ __nv_bfloat16 g_big [401408 * 768];
__device__ float         g_xnew[401408 * 192];
// bf16 weights (converted once per launch)
__device__ __nv_bfloat16 g_wqkv[192 * 576];
__device__ __nv_bfloat16 g_wproj[192 * 192];
__device__ __nv_bfloat16 g_w1 [192 * 768];
__device__ __nv_bfloat16 g_w2 [768 * 192];

__device__ __forceinline__ uint32_t smem_u32(const void* p) {
    return (uint32_t)__cvta_generic_to_shared(p);
}
__device__ __forceinline__ void cp16(void* sdst, const void* gsrc) {
    asm volatile("cp.async.cg.shared.global [%0], [%1], 16;\n"
                 :: "r"(smem_u32(sdst)), "l"(gsrc));
}
__device__ __forceinline__ void cp_commit() {
    asm volatile("cp.async.commit_group;\n");
}
template <int N>
__device__ __forceinline__ void cp_wait() {
    asm volatile("cp.async.wait_group %0;\n" :: "n"(N));
}

// ---------------------------------------------------------------------------
// fp32 -> bf16 weight convert
// ---------------------------------------------------------------------------
__global__ void f2bf_k(const float* __restrict__ s, __nv_bfloat16* __restrict__ d, int n) {
    int i = blockIdx.x * 256 + threadIdx.x;
    if (i < n) d[i] = __float2bfloat16(s[i]);
}

// ---------------------------------------------------------------------------
// LN: one warp per token, bf16 output
// ---------------------------------------------------------------------------
__device__ __forceinline__ void warp_ln_row(const float* __restrict__ src,
                                            const float* __restrict__ w,
                                            const float* __restrict__ b,
                                            __nv_bfloat16* __restrict__ dst,
                                            int lane) {
    float v[6];
    float s = 0.f, ss = 0.f;
#pragma unroll
    for (int t = 0; t < 6; t++) {
        v[t] = src[lane + 32 * t];
        s += v[t];
        ss += v[t] * v[t];
    }
#pragma unroll
    for (int o = 16; o > 0; o >>= 1) {
        s  += __shfl_xor_sync(0xffffffffu, s,  o);
        ss += __shfl_xor_sync(0xffffffffu, ss, o);
    }
    float mu  = s * (1.f / 192.f);
    float var = ss * (1.f / 192.f) - mu * mu;
    float inv = rsqrtf(var + 1e-5f);
#pragma unroll
    for (int t = 0; t < 6; t++) {
        int c = lane + 32 * t;
        dst[c] = __float2bfloat16((v[t] - mu) * inv * w[c] + b[c]);
    }
}

__device__ __forceinline__ long long token_to_pixel_row(int token) {
    int bb  = token / (NWIN_ * NTOK_);
    int rem = token - bb * (NWIN_ * NTOK_);
    int wi  = rem / NTOK_;
    int n   = rem - wi * NTOK_;
    int wh = wi >> 5, ww = wi & 31;
    int r = n / 7, c = n - r * 7;
    int hh = wh * 7 + r + SHIFT_; if (hh >= HW_) hh -= HW_;
    int wp = ww * 7 + c + SHIFT_; if (wp >= HW_) wp -= HW_;
    return (long long)bb * (HW_ * HW_) + hh * HW_ + wp;
}

__global__ __launch_bounds__(256)
void ln1_window_k(const float* __restrict__ x,
                  const float* __restrict__ w, const float* __restrict__ b,
                  __nv_bfloat16* __restrict__ out) {
    int token = blockIdx.x * 8 + (threadIdx.x >> 5);
    int lane  = threadIdx.x & 31;
    long long src_row = token_to_pixel_row(token);
    warp_ln_row(x + src_row * C_, w, b, out + (long long)token * C_, lane);
}

__global__ __launch_bounds__(256)
void ln2_k(const float* __restrict__ x,
           const float* __restrict__ w, const float* __restrict__ b,
           __nv_bfloat16* __restrict__ out) {
    int token = blockIdx.x * 8 + (threadIdx.x >> 5);
    int lane  = threadIdx.x & 31;
    warp_ln_row(x + (long long)token * C_, w, b, out + (long long)token * C_, lane);
}

// ---------------------------------------------------------------------------
// BF16 tensor-core GEMM with 3-stage cp.async pipeline
// C = A(bf16)[M,K] @ B(bf16)[K,N] + bias
//   EPI 0: bias -> bf16          EPI 1: bias+GELU -> bf16
//   EPI 2: bias+scatter+residual -> fp32   EPI 3: bias+residual -> fp32
// BM=128 BN=64 BK=32; 8 warps (4m x 2n); warp tile 32x32; m16n8k16.
// ---------------------------------------------------------------------------
#define APAD 8
#define BPAD 8
#define STAGES 3

template <int EPI>
__global__ __launch_bounds__(256, 2)
void bgemm_k(const __nv_bfloat16* __restrict__ A, const __nv_bfloat16* __restrict__ Bw,
             const float* __restrict__ bias, void* __restrict__ Cout,
             int M, int N, int K, const float* __restrict__ res) {
    const int BM = 128, BN = 64, BK = 32;
    __shared__ __nv_bfloat16 As[STAGES][BM][BK + APAD];
    __shared__ __nv_bfloat16 Bs[STAGES][BK][BN + BPAD];

    int tid  = threadIdx.x;
    int warp = tid >> 5, lane = tid & 31;
    int wm = warp & 3, wn = warp >> 2;

    int brow = blockIdx.y, bcol = blockIdx.x;
    const __nv_bfloat16* Ab = A  + (size_t)brow * BM * K;
    const __nv_bfloat16* Bb = Bw + bcol * BN;

    // load indices
    int am = tid >> 2, acq = (tid & 3) * 8;          // A: 2 chunks (tid, tid+256)
    int am2 = (tid + 256) >> 2, acq2 = ((tid + 256) & 3) * 8;
    int bk = tid >> 3, bnq = (tid & 7) * 8;          // B: 1 chunk

    float acc[2][4][4];
#pragma unroll
    for (int i = 0; i < 2; i++)
#pragma unroll
        for (int j = 0; j < 4; j++)
#pragma unroll
            for (int l = 0; l < 4; l++) acc[i][j][l] = 0.f;

    const int ntiles = K / BK;

    // prologue: issue STAGES-1 tile loads
#pragma unroll
    for (int s = 0; s < STAGES - 1; s++) {
        int k0 = s * BK;
        cp16(&As[s][am ][acq ], Ab + (size_t)am  * K + k0 + acq );
        cp16(&As[s][am2][acq2], Ab + (size_t)am2 * K + k0 + acq2);
        cp16(&Bs[s][bk][bnq], Bb + (size_t)(k0 + bk) * N + bnq);
        cp_commit();
    }

    int a_row_lane = ((lane >> 3) & 1) * 8 + (lane & 7);
    int a_kof_lane = (lane >> 4) * 8;

    int stage = 0;
    for (int t = 0; t < ntiles; t++) {
        cp_wait<STAGES - 2>();
        __syncthreads();

        // issue load for tile t+STAGES-1
        int tn = t + STAGES - 1;
        if (tn < ntiles) {
            int sn = stage + STAGES - 1; if (sn >= STAGES) sn -= STAGES;
            int k0 = tn * BK;
            cp16(&As[sn][am ][acq ], Ab + (size_t)am  * K + k0 + acq );
            cp16(&As[sn][am2][acq2], Ab + (size_t)am2 * K + k0 + acq2);
            cp16(&Bs[sn][bk][bnq], Bb + (size_t)(k0 + bk) * N + bnq);
        }
        cp_commit();

        // compute tile t from smem stage
#pragma unroll
        for (int ks = 0; ks < 2; ks++) {
            int kk = ks * 16;
            uint32_t af[2][4], bfr[2][4];
#pragma unroll
            for (int mi = 0; mi < 2; mi++) {
                int mrow = wm * 32 + mi * 16 + a_row_lane;
                uint32_t addr = smem_u32(&As[stage][mrow][kk + a_kof_lane]);
                asm volatile("ldmatrix.sync.aligned.m8n8.x4.shared.b16 "
                             "{%0,%1,%2,%3}, [%4];"
                             : "=r"(af[mi][0]), "=r"(af[mi][1]),
                               "=r"(af[mi][2]), "=r"(af[mi][3])
                             : "r"(addr));
            }
#pragma unroll
            for (int ng = 0; ng < 2; ng++) {
                int ncol = wn * 32 + ng * 16 + a_kof_lane;
                uint32_t addr = smem_u32(&Bs[stage][kk + a_row_lane][ncol]);
                asm volatile("ldmatrix.sync.aligned.m8n8.x4.trans.shared.b16 "
                             "{%0,%1,%2,%3}, [%4];"
                             : "=r"(bfr[ng][0]), "=r"(bfr[ng][1]),
                               "=r"(bfr[ng][2]), "=r"(bfr[ng][3])
                             : "r"(addr));
            }
#pragma unroll
            for (int mi = 0; mi < 2; mi++)
#pragma unroll
                for (int ni = 0; ni < 4; ni++) {
                    uint32_t b0 = bfr[ni >> 1][(ni & 1) * 2 + 0];
                    uint32_t b1 = bfr[ni >> 1][(ni & 1) * 2 + 1];
                    asm volatile(
                        "mma.sync.aligned.m16n8k16.row.col.f32.bf16.bf16.f32 "
                        "{%0,%1,%2,%3}, {%4,%5,%6,%7}, {%8,%9}, {%0,%1,%2,%3};"
                        : "+f"(acc[mi][ni][0]), "+f"(acc[mi][ni][1]),
                          "+f"(acc[mi][ni][2]), "+f"(acc[mi][ni][3])
                        : "r"(af[mi][0]), "r"(af[mi][1]),
                          "r"(af[mi][2]), "r"(af[mi][3]),
                          "r"(b0), "r"(b1));
                }
        }
        __syncthreads();
        stage = stage + 1; if (stage >= STAGES) stage -= STAGES;
    }

    // ------------------------------ epilogue ------------------------------
    int g  = lane >> 2;
    int tg = lane & 3;
#pragma unroll
    for (int mi = 0; mi < 2; mi++) {
        int row0 = brow * BM + wm * 32 + mi * 16 + g;
        int row1 = row0 + 8;
        long long d0 = 0, d1 = 0;
        if (EPI == 2) { d0 = token_to_pixel_row(row0); d1 = token_to_pixel_row(row1); }
#pragma unroll
        for (int ni = 0; ni < 4; ni++) {
            int col = bcol * BN + wn * 32 + ni * 8 + tg * 2;
            float bx = bias[col], by = bias[col + 1];
            float v0 = acc[mi][ni][0] + bx, v1 = acc[mi][ni][1] + by;
            float v2 = acc[mi][ni][2] + bx, v3 = acc[mi][ni][3] + by;
            if (EPI == 1) {
                v0 = 0.5f * v0 * (1.f + erff(v0 * 0.70710678118654752f));
                v1 = 0.5f * v1 * (1.f + erff(v1 * 0.70710678118654752f));
                v2 = 0.5f * v2 * (1.f + erff(v2 * 0.70710678118654752f));
                v3 = 0.5f * v3 * (1.f + erff(v3 * 0.70710678118654752f));
            }
            if (EPI == 0 || EPI == 1) {
                __nv_bfloat16* C = (__nv_bfloat16*)Cout;
                *(__nv_bfloat162*)(C + (size_t)row0 * N + col) = __floats2bfloat162_rn(v0, v1);
                *(__nv_bfloat162*)(C + (size_t)row1 * N + col) = __floats2bfloat162_rn(v2, v3);
            } else if (EPI == 2) {
                float* C = (float*)Cout;
                float2 r0 = *(const float2*)(res + d0 * C_ + col);
                float2 r1 = *(const float2*)(res + d1 * C_ + col);
                *(float2*)(C + d0 * C_ + col) = make_float2(v0 + r0.x, v1 + r0.y);
                *(float2*)(C + d1 * C_ + col) = make_float2(v2 + r1.x, v3 + r1.y);
            } else {
                float* C = (float*)Cout;
                float2 r0 = *(const float2*)(res + (size_t)row0 * N + col);
                float2 r1 = *(const float2*)(res + (size_t)row1 * N + col);
                *(float2*)(C + (size_t)row0 * N + col) = make_float2(v0 + r0.x, v1 + r0.y);
                *(float2*)(C + (size_t)row1 * N + col) = make_float2(v2 + r1.x, v3 + r1.y);
            }
        }
    }
}

// ---------------------------------------------------------------------------
// Windowed attention (bf16 in/out, fp32 math)
// ---------------------------------------------------------------------------
__global__ __launch_bounds__(128)
void attn_k(const __nv_bfloat16* __restrict__ qkv, const float* __restrict__ rpb,
            __nv_bfloat16* __restrict__ out) {
    int wg = blockIdx.x;
    int h  = blockIdx.y;
    int wi = wg & (NWIN_ - 1);
    int wh = wi >> 5, ww = wi & 31;

    __shared__ float sq[49][33], sk[49][33], sv[49][33];
    __shared__ float sp[4][49];
    __shared__ int   sreg[49];

    int tid = threadIdx.x;
    long long base = (long long)wg * NTOK_ * 576 + h * HD_;

    for (int idx = tid; idx < 49 * 32; idx += 128) {
        int n = idx >> 5, d = idx & 31;
        long long rb = base + (long long)n * 576 + d;
        sq[n][d] = __bfloat162float(qkv[rb]);
        sk[n][d] = __bfloat162float(qkv[rb + 192]);
        sv[n][d] = __bfloat162float(qkv[rb + 384]);
    }
    if (tid < 49) {
        int r = tid / 7, c = tid - (tid / 7) * 7;
        int gh = wh * 7 + r, gw = ww * 7 + c;
        int hid = gh < (HW_ - WS_) ? 0 : (gh < (HW_ - SHIFT_) ? 1 : 2);
        int wid = gw < (HW_ - WS_) ? 0 : (gw < (HW_ - SHIFT_) ? 1 : 2);
        sreg[tid] = hid * 3 + wid;
    }
    __syncthreads();

    int warp = tid >> 5, lane = tid & 31;
    const float scale = 0.1767766952966369f;

    for (int i = warp; i < 49; i += 4) {
        int r1 = i / 7, c1 = i - (i / 7) * 7;
        int regi = sreg[i];

        float s1, s2 = -1e30f;
        {
            int j = lane;
            float dp = 0.f;
#pragma unroll
            for (int d = 0; d < 32; d++) dp += sq[i][d] * sk[j][d];
            int r2 = j / 7, c2 = j - (j / 7) * 7;
            int rel = (r1 - r2 + 6) * 13 + (c1 - c2 + 6);
            float bv = rpb[rel * NH_ + h];
            float mk = (sreg[j] != regi) ? -100.f : 0.f;
            s1 = dp * scale + bv + mk;
        }
        if (lane < 17) {
            int j = lane + 32;
            float dp = 0.f;
#pragma unroll
            for (int d = 0; d < 32; d++) dp += sq[i][d] * sk[j][d];
            int r2 = j / 7, c2 = j - (j / 7) * 7;
            int rel = (r1 - r2 + 6) * 13 + (c1 - c2 + 6);
            float bv = rpb[rel * NH_ + h];
            float mk = (sreg[j] != regi) ? -100.f : 0.f;
            s2 = dp * scale + bv + mk;
        }
        float mx = fmaxf(s1, s2);
#pragma unroll
        for (int o = 16; o > 0; o >>= 1)
            mx = fmaxf(mx, __shfl_xor_sync(0xffffffffu, mx, o));
        float e1 = __expf(s1 - mx);
        float e2 = (lane < 17) ? __expf(s2 - mx) : 0.f;
        float sum = e1 + e2;
#pragma unroll
        for (int o = 16; o > 0; o >>= 1)
            sum += __shfl_xor_sync(0xffffffffu, sum, o);
        float inv = 1.f / sum;
        sp[warp][lane] = e1 * inv;
        if (lane < 17) sp[warp][lane + 32] = e2 * inv;
        __syncwarp();

        float acc = 0.f;
#pragma unroll 7
        for (int j = 0; j < 49; j++) acc += sp[warp][j] * sv[j][lane];

        long long orow = ((long long)wg * NTOK_ + i) * C_ + h * HD_ + lane;
        out[orow] = __float2bfloat16(acc);
        __syncwarp();
    }
}

// ---------------------------------------------------------------------------
// Launch
// ---------------------------------------------------------------------------
extern "C" void kernel_launch(void* const* d_in, const int* in_sizes, int n_in,
                              void* d_out, int out_size) {
    const float* x      = (const float*)d_in[0];
    const float* qkv_w  = (const float*)d_in[3];
    const float* qkv_b  = (const float*)d_in[4];
    const float* proj_w = (const float*)d_in[5];
    const float* proj_b = (const float*)d_in[6];
    const float* rpb    = (const float*)d_in[7];
    const float* n1w    = (const float*)d_in[8];
    const float* n1b    = (const float*)d_in[9];
    const float* n2w    = (const float*)d_in[10];
    const float* n2b    = (const float*)d_in[11];
    const float* w1     = (const float*)d_in[12];
    const float* b1     = (const float*)d_in[13];
    const float* w2     = (const float*)d_in[14];
    const float* b2     = (const float*)d_in[15];
    float* out = (float*)d_out;

    __nv_bfloat16 *win = nullptr, *big = nullptr;
    __nv_bfloat16 *wqkv = nullptr, *wproj = nullptr, *bw1 = nullptr, *bw2 = nullptr;
    float *xnew = nullptr;
    cudaGetSymbolAddress((void**)&win,   g_win);
    cudaGetSymbolAddress((void**)&big,   g_big);
    cudaGetSymbolAddress((void**)&xnew,  g_xnew);
    cudaGetSymbolAddress((void**)&wqkv,  g_wqkv);
    cudaGetSymbolAddress((void**)&wproj, g_wproj);
    cudaGetSymbolAddress((void**)&bw1,   g_w1);
    cudaGetSymbolAddress((void**)&bw2,   g_w2);

    const int M = M_TOK;
    const int MB = M / 128;

    // weight conversion (cheap)
    f2bf_k<<<(192 * 576 + 255) / 256, 256>>>(qkv_w,  wqkv,  192 * 576);
    f2bf_k<<<(192 * 192 + 255) / 256, 256>>>(proj_w, wproj, 192 * 192);
    f2bf_k<<<(192 * 768 + 255) / 256, 256>>>(w1,     bw1,   192 * 768);
    f2bf_k<<<(768 * 192 + 255) / 256, 256>>>(w2,     bw2,   768 * 192);

    ln1_window_k<<<M / 8, 256>>>(x, n1w, n1b, win);
    bgemm_k<0><<<dim3(576 / 64, MB), 256>>>(win, wqkv, qkv_b, big, M, 576, 192, nullptr);
    attn_k<<<dim3(B_ * NWIN_, NH_), 128>>>(big, rpb, win);
    bgemm_k<2><<<dim3(192 / 64, MB), 256>>>(win, wproj, proj_b, xnew, M, 192, 192, x);
    ln2_k<<<M / 8, 256>>>(xnew, n2w, n2b, win);
    bgemm_k<1><<<dim3(768 / 64, MB), 256>>>(win, bw1, b1, big, M, 768, 192, nullptr);
    bgemm_k<3><<<dim3(192 / 64, MB), 256>>>(big, bw2, b2, out, M, 192, 768, xnew);
}

// round 11
// speedup vs baseline: 1.0024x; 1.0005x over previous
#include <cuda_runtime.h>
#include <cuda_bf16.h>
#include <math.h>
#include <stdint.h>

// ---------------------------------------------------------------------------
// Problem constants
// ---------------------------------------------------------------------------
#define B_   8
#define HW_  224
#define C_   192
#define WS_  7
#define SHIFT_ 3
#define NH_  6
#define HD_  32
#define NWIN_ 1024
#define NTOK_ 49
#define M_TOK 401408
#define DFF_ 768

// ---------------------------------------------------------------------------
// Scratch
// ---------------------------------------------------------------------------
__device__ __nv_bfloat16 g_win [401408 * 192];
__device__ __nv_bfloat16 g_big [401408 * 768];
__device__ float         g_xnew[401408 * 192];
// bf16 weights (converted once per launch)
__device__ __nv_bfloat16 g_wqkv[192 * 576];
__device__ __nv_bfloat16 g_wproj[192 * 192];
__device__ __nv_bfloat16 g_w1 [192 * 768];
__device__ __nv_bfloat16 g_w2 [768 * 192];

__device__ __forceinline__ uint32_t smem_u32(const void* p) {
    return (uint32_t)__cvta_generic_to_shared(p);
}
__device__ __forceinline__ void cp16(void* sdst, const void* gsrc) {
    asm volatile("cp.async.cg.shared.global [%0], [%1], 16;\n"
                 :: "r"(smem_u32(sdst)), "l"(gsrc));
}
__device__ __forceinline__ void cp_commit() {
    asm volatile("cp.async.commit_group;\n");
}
template <int N>
__device__ __forceinline__ void cp_wait() {
    asm volatile("cp.async.wait_group %0;\n" :: "n"(N));
}

// ---------------------------------------------------------------------------
// fp32 -> bf16 weight convert
// ---------------------------------------------------------------------------
__global__ void f2bf_k(const float* __restrict__ s, __nv_bfloat16* __restrict__ d, int n) {
    int i = blockIdx.x * 256 + threadIdx.x;
    if (i < n) d[i] = __float2bfloat16(s[i]);
}

// ---------------------------------------------------------------------------
// LN: one warp per token, bf16 output
// ---------------------------------------------------------------------------
__device__ __forceinline__ void warp_ln_row(const float* __restrict__ src,
                                            const float* __restrict__ w,
                                            const float* __restrict__ b,
                                            __nv_bfloat16* __restrict__ dst,
                                            int lane) {
    float v[6];
    float s = 0.f, ss = 0.f;
#pragma unroll
    for (int t = 0; t < 6; t++) {
        v[t] = src[lane + 32 * t];
        s += v[t];
        ss += v[t] * v[t];
    }
#pragma unroll
    for (int o = 16; o > 0; o >>= 1) {
        s  += __shfl_xor_sync(0xffffffffu, s,  o);
        ss += __shfl_xor_sync(0xffffffffu, ss, o);
    }
    float mu  = s * (1.f / 192.f);
    float var = ss * (1.f / 192.f) - mu * mu;
    float inv = rsqrtf(var + 1e-5f);
#pragma unroll
    for (int t = 0; t < 6; t++) {
        int c = lane + 32 * t;
        dst[c] = __float2bfloat16((v[t] - mu) * inv * w[c] + b[c]);
    }
}

__device__ __forceinline__ long long token_to_pixel_row(int token) {
    int bb  = token / (NWIN_ * NTOK_);
    int rem = token - bb * (NWIN_ * NTOK_);
    int wi  = rem / NTOK_;
    int n   = rem - wi * NTOK_;
    int wh = wi >> 5, ww = wi & 31;
    int r = n / 7, c = n - r * 7;
    int hh = wh * 7 + r + SHIFT_; if (hh >= HW_) hh -= HW_;
    int wp = ww * 7 + c + SHIFT_; if (wp >= HW_) wp -= HW_;
    return (long long)bb * (HW_ * HW_) + hh * HW_ + wp;
}

__global__ __launch_bounds__(256)
void ln1_window_k(const float* __restrict__ x,
                  const float* __restrict__ w, const float* __restrict__ b,
                  __nv_bfloat16* __restrict__ out) {
    int token = blockIdx.x * 8 + (threadIdx.x >> 5);
    int lane  = threadIdx.x & 31;
    long long src_row = token_to_pixel_row(token);
    warp_ln_row(x + src_row * C_, w, b, out + (long long)token * C_, lane);
}

__global__ __launch_bounds__(256)
void ln2_k(const float* __restrict__ x,
           const float* __restrict__ w, const float* __restrict__ b,
           __nv_bfloat16* __restrict__ out) {
    int token = blockIdx.x * 8 + (threadIdx.x >> 5);
    int lane  = threadIdx.x & 31;
    warp_ln_row(x + (long long)token * C_, w, b, out + (long long)token * C_, lane);
}

// ---------------------------------------------------------------------------
// BF16 tensor-core GEMM with 3-stage cp.async pipeline
// C = A(bf16)[M,K] @ B(bf16)[K,N] + bias
//   EPI 0: bias -> bf16          EPI 1: bias+GELU -> bf16
//   EPI 2: bias+scatter+residual -> fp32   EPI 3: bias+residual -> fp32
// BM=128 BN=64 BK=32; 8 warps (4m x 2n); warp tile 32x32; m16n8k16.
// ---------------------------------------------------------------------------
#define APAD 8
#define BPAD 8
#define STAGES 3

template <int EPI>
__global__ __launch_bounds__(256, 2)
void bgemm_k(const __nv_bfloat16* __restrict__ A, const __nv_bfloat16* __restrict__ Bw,
             const float* __restrict__ bias, void* __restrict__ Cout,
             int M, int N, int K, const float* __restrict__ res) {
    const int BM = 128, BN = 64, BK = 32;
    __shared__ __nv_bfloat16 As[STAGES][BM][BK + APAD];
    __shared__ __nv_bfloat16 Bs[STAGES][BK][BN + BPAD];

    int tid  = threadIdx.x;
    int warp = tid >> 5, lane = tid & 31;
    int wm = warp & 3, wn = warp >> 2;

    int brow = blockIdx.y, bcol = blockIdx.x;
    const __nv_bfloat16* Ab = A  + (size_t)brow * BM * K;
    const __nv_bfloat16* Bb = Bw + bcol * BN;

    // load indices
    int am = tid >> 2, acq = (tid & 3) * 8;          // A: 2 chunks (tid, tid+256)
    int am2 = (tid + 256) >> 2, acq2 = ((tid + 256) & 3) * 8;
    int bk = tid >> 3, bnq = (tid & 7) * 8;          // B: 1 chunk

    float acc[2][4][4];
#pragma unroll
    for (int i = 0; i < 2; i++)
#pragma unroll
        for (int j = 0; j < 4; j++)
#pragma unroll
            for (int l = 0; l < 4; l++) acc[i][j][l] = 0.f;

    const int ntiles = K / BK;

    // prologue: issue STAGES-1 tile loads
#pragma unroll
    for (int s = 0; s < STAGES - 1; s++) {
        int k0 = s * BK;
        cp16(&As[s][am ][acq ], Ab + (size_t)am  * K + k0 + acq );
        cp16(&As[s][am2][acq2], Ab + (size_t)am2 * K + k0 + acq2);
        cp16(&Bs[s][bk][bnq], Bb + (size_t)(k0 + bk) * N + bnq);
        cp_commit();
    }

    int a_row_lane = ((lane >> 3) & 1) * 8 + (lane & 7);
    int a_kof_lane = (lane >> 4) * 8;

    int stage = 0;
    for (int t = 0; t < ntiles; t++) {
        cp_wait<STAGES - 2>();
        __syncthreads();

        // issue load for tile t+STAGES-1
        int tn = t + STAGES - 1;
        if (tn < ntiles) {
            int sn = stage + STAGES - 1; if (sn >= STAGES) sn -= STAGES;
            int k0 = tn * BK;
            cp16(&As[sn][am ][acq ], Ab + (size_t)am  * K + k0 + acq );
            cp16(&As[sn][am2][acq2], Ab + (size_t)am2 * K + k0 + acq2);
            cp16(&Bs[sn][bk][bnq], Bb + (size_t)(k0 + bk) * N + bnq);
        }
        cp_commit();

        // compute tile t from smem stage
#pragma unroll
        for (int ks = 0; ks < 2; ks++) {
            int kk = ks * 16;
            uint32_t af[2][4], bfr[2][4];
#pragma unroll
            for (int mi = 0; mi < 2; mi++) {
                int mrow = wm * 32 + mi * 16 + a_row_lane;
                uint32_t addr = smem_u32(&As[stage][mrow][kk + a_kof_lane]);
                asm volatile("ldmatrix.sync.aligned.m8n8.x4.shared.b16 "
                             "{%0,%1,%2,%3}, [%4];"
                             : "=r"(af[mi][0]), "=r"(af[mi][1]),
                               "=r"(af[mi][2]), "=r"(af[mi][3])
                             : "r"(addr));
            }
#pragma unroll
            for (int ng = 0; ng < 2; ng++) {
                int ncol = wn * 32 + ng * 16 + a_kof_lane;
                uint32_t addr = smem_u32(&Bs[stage][kk + a_row_lane][ncol]);
                asm volatile("ldmatrix.sync.aligned.m8n8.x4.trans.shared.b16 "
                             "{%0,%1,%2,%3}, [%4];"
                             : "=r"(bfr[ng][0]), "=r"(bfr[ng][1]),
                               "=r"(bfr[ng][2]), "=r"(bfr[ng][3])
                             : "r"(addr));
            }
#pragma unroll
            for (int mi = 0; mi < 2; mi++)
#pragma unroll
                for (int ni = 0; ni < 4; ni++) {
                    uint32_t b0 = bfr[ni >> 1][(ni & 1) * 2 + 0];
                    uint32_t b1 = bfr[ni >> 1][(ni & 1) * 2 + 1];
                    asm volatile(
                        "mma.sync.aligned.m16n8k16.row.col.f32.bf16.bf16.f32 "
                        "{%0,%1,%2,%3}, {%4,%5,%6,%7}, {%8,%9}, {%0,%1,%2,%3};"
                        : "+f"(acc[mi][ni][0]), "+f"(acc[mi][ni][1]),
                          "+f"(acc[mi][ni][2]), "+f"(acc[mi][ni][3])
                        : "r"(af[mi][0]), "r"(af[mi][1]),
                          "r"(af[mi][2]), "r"(af[mi][3]),
                          "r"(b0), "r"(b1));
                }
        }
        __syncthreads();
        stage = stage + 1; if (stage >= STAGES) stage -= STAGES;
    }

    // ------------------------------ epilogue ------------------------------
    int g  = lane >> 2;
    int tg = lane & 3;
#pragma unroll
    for (int mi = 0; mi < 2; mi++) {
        int row0 = brow * BM + wm * 32 + mi * 16 + g;
        int row1 = row0 + 8;
        long long d0 = 0, d1 = 0;
        if (EPI == 2) { d0 = token_to_pixel_row(row0); d1 = token_to_pixel_row(row1); }
#pragma unroll
        for (int ni = 0; ni < 4; ni++) {
            int col = bcol * BN + wn * 32 + ni * 8 + tg * 2;
            float bx = bias[col], by = bias[col + 1];
            float v0 = acc[mi][ni][0] + bx, v1 = acc[mi][ni][1] + by;
            float v2 = acc[mi][ni][2] + bx, v3 = acc[mi][ni][3] + by;
            if (EPI == 1) {
                v0 = 0.5f * v0 * (1.f + erff(v0 * 0.70710678118654752f));
                v1 = 0.5f * v1 * (1.f + erff(v1 * 0.70710678118654752f));
                v2 = 0.5f * v2 * (1.f + erff(v2 * 0.70710678118654752f));
                v3 = 0.5f * v3 * (1.f + erff(v3 * 0.70710678118654752f));
            }
            if (EPI == 0 || EPI == 1) {
                __nv_bfloat16* C = (__nv_bfloat16*)Cout;
                *(__nv_bfloat162*)(C + (size_t)row0 * N + col) = __floats2bfloat162_rn(v0, v1);
                *(__nv_bfloat162*)(C + (size_t)row1 * N + col) = __floats2bfloat162_rn(v2, v3);
            } else if (EPI == 2) {
                float* C = (float*)Cout;
                float2 r0 = *(const float2*)(res + d0 * C_ + col);
                float2 r1 = *(const float2*)(res + d1 * C_ + col);
                *(float2*)(C + d0 * C_ + col) = make_float2(v0 + r0.x, v1 + r0.y);
                *(float2*)(C + d1 * C_ + col) = make_float2(v2 + r1.x, v3 + r1.y);
            } else {
                float* C = (float*)Cout;
                float2 r0 = *(const float2*)(res + (size_t)row0 * N + col);
                float2 r1 = *(const float2*)(res + (size_t)row1 * N + col);
                *(float2*)(C + (size_t)row0 * N + col) = make_float2(v0 + r0.x, v1 + r0.y);
                *(float2*)(C + (size_t)row1 * N + col) = make_float2(v2 + r1.x, v3 + r1.y);
            }
        }
    }
}

// ---------------------------------------------------------------------------
// Windowed attention (bf16 in/out, fp32 math)
// ---------------------------------------------------------------------------
__global__ __launch_bounds__(128)
void attn_k(const __nv_bfloat16* __restrict__ qkv, const float* __restrict__ rpb,
            __nv_bfloat16* __restrict__ out) {
    int wg = blockIdx.x;
    int h  = blockIdx.y;
    int wi = wg & (NWIN_ - 1);
    int wh = wi >> 5, ww = wi & 31;

    __shared__ float sq[49][33], sk[49][33], sv[49][33];
    __shared__ float sp[4][49];
    __shared__ int   sreg[49];

    int tid = threadIdx.x;
    long long base = (long long)wg * NTOK_ * 576 + h * HD_;

    for (int idx = tid; idx < 49 * 32; idx += 128) {
        int n = idx >> 5, d = idx & 31;
        long long rb = base + (long long)n * 576 + d;
        sq[n][d] = __bfloat162float(qkv[rb]);
        sk[n][d] = __bfloat162float(qkv[rb + 192]);
        sv[n][d] = __bfloat162float(qkv[rb + 384]);
    }
    if (tid < 49) {
        int r = tid / 7, c = tid - (tid / 7) * 7;
        int gh = wh * 7 + r, gw = ww * 7 + c;
        int hid = gh < (HW_ - WS_) ? 0 : (gh < (HW_ - SHIFT_) ? 1 : 2);
        int wid = gw < (HW_ - WS_) ? 0 : (gw < (HW_ - SHIFT_) ? 1 : 2);
        sreg[tid] = hid * 3 + wid;
    }
    __syncthreads();

    int warp = tid >> 5, lane = tid & 31;
    const float scale = 0.1767766952966369f;

    for (int i = warp; i < 49; i += 4) {
        int r1 = i / 7, c1 = i - (i / 7) * 7;
        int regi = sreg[i];

        float s1, s2 = -1e30f;
        {
            int j = lane;
            float dp = 0.f;
#pragma unroll
            for (int d = 0; d < 32; d++) dp += sq[i][d] * sk[j][d];
            int r2 = j / 7, c2 = j - (j / 7) * 7;
            int rel = (r1 - r2 + 6) * 13 + (c1 - c2 + 6);
            float bv = rpb[rel * NH_ + h];
            float mk = (sreg[j] != regi) ? -100.f : 0.f;
            s1 = dp * scale + bv + mk;
        }
        if (lane < 17) {
            int j = lane + 32;
            float dp = 0.f;
#pragma unroll
            for (int d = 0; d < 32; d++) dp += sq[i][d] * sk[j][d];
            int r2 = j / 7, c2 = j - (j / 7) * 7;
            int rel = (r1 - r2 + 6) * 13 + (c1 - c2 + 6);
            float bv = rpb[rel * NH_ + h];
            float mk = (sreg[j] != regi) ? -100.f : 0.f;
            s2 = dp * scale + bv + mk;
        }
        float mx = fmaxf(s1, s2);
#pragma unroll
        for (int o = 16; o > 0; o >>= 1)
            mx = fmaxf(mx, __shfl_xor_sync(0xffffffffu, mx, o));
        float e1 = __expf(s1 - mx);
        float e2 = (lane < 17) ? __expf(s2 - mx) : 0.f;
        float sum = e1 + e2;
#pragma unroll
        for (int o = 16; o > 0; o >>= 1)
            sum += __shfl_xor_sync(0xffffffffu, sum, o);
        float inv = 1.f / sum;
        sp[warp][lane] = e1 * inv;
        if (lane < 17) sp[warp][lane + 32] = e2 * inv;
        __syncwarp();

        float acc = 0.f;
#pragma unroll 7
        for (int j = 0; j < 49; j++) acc += sp[warp][j] * sv[j][lane];

        long long orow = ((long long)wg * NTOK_ + i) * C_ + h * HD_ + lane;
        out[orow] = __float2bfloat16(acc);
        __syncwarp();
    }
}

// ---------------------------------------------------------------------------
// Launch
// ---------------------------------------------------------------------------
extern "C" void kernel_launch(void* const* d_in, const int* in_sizes, int n_in,
                              void* d_out, int out_size) {
    const float* x      = (const float*)d_in[0];
    const float* qkv_w  = (const float*)d_in[3];
    const float* qkv_b  = (const float*)d_in[4];
    const float* proj_w = (const float*)d_in[5];
    const float* proj_b = (const float*)d_in[6];
    const float* rpb    = (const float*)d_in[7];
    const float* n1w    = (const float*)d_in[8];
    const float* n1b    = (const float*)d_in[9];
    const float* n2w    = (const float*)d_in[10];
    const float* n2b    = (const float*)d_in[11];
    const float* w1     = (const float*)d_in[12];
    const float* b1     = (const float*)d_in[13];
    const float* w2     = (const float*)d_in[14];
    const float* b2     = (const float*)d_in[15];
    float* out = (float*)d_out;

    __nv_bfloat16 *win = nullptr, *big = nullptr;
    __nv_bfloat16 *wqkv = nullptr, *wproj = nullptr, *bw1 = nullptr, *bw2 = nullptr;
    float *xnew = nullptr;
    cudaGetSymbolAddress((void**)&win,   g_win);
    cudaGetSymbolAddress((void**)&big,   g_big);
    cudaGetSymbolAddress((void**)&xnew,  g_xnew);
    cudaGetSymbolAddress((void**)&wqkv,  g_wqkv);
    cudaGetSymbolAddress((void**)&wproj, g_wproj);
    cudaGetSymbolAddress((void**)&bw1,   g_w1);
    cudaGetSymbolAddress((void**)&bw2,   g_w2);

    const int M = M_TOK;
    const int MB = M / 128;

    // weight conversion (cheap)
    f2bf_k<<<(192 * 576 + 255) / 256, 256>>>(qkv_w,  wqkv,  192 * 576);
    f2bf_k<<<(192 * 192 + 255) / 256, 256>>>(proj_w, wproj, 192 * 192);
    f2bf_k<<<(192 * 768 + 255) / 256, 256>>>(w1,     bw1,   192 * 768);
    f2bf_k<<<(768 * 192 + 255) / 256, 256>>>(w2,     bw2,   768 * 192);

    ln1_window_k<<<M / 8, 256>>>(x, n1w, n1b, win);
    bgemm_k<0><<<dim3(576 / 64, MB), 256>>>(win, wqkv, qkv_b, big, M, 576, 192, nullptr);
    attn_k<<<dim3(B_ * NWIN_, NH_), 128>>>(big, rpb, win);
    bgemm_k<2><<<dim3(192 / 64, MB), 256>>>(win, wproj, proj_b, xnew, M, 192, 192, x);
    ln2_k<<<M / 8, 256>>>(xnew, n2w, n2b, win);
    bgemm_k<1><<<dim3(768 / 64, MB), 256>>>(win, bw1, b1, big, M, 768, 192, nullptr);
    bgemm_k<3><<<dim3(192 / 64, MB), 256>>>(big, bw2, b2, out, M, 192, 768, xnew);
}